// round 6
// baseline (speedup 1.0000x reference)
#include <cuda_runtime.h>
#include <cuda_fp16.h>
#include <math.h>
#include <stdint.h>

#define N_LEVELS 16
#define HASH_MASK 32767u
#define HASHMAP_SIZE 32768
#define N_RANGES 9             // 16 levels * 9 ranges = 144 CTAs = 1 wave on 148 SMs
#define CTA_THREADS 1024
#define MAX_POINTS 2000000

#define TP_THREADS 512
#define TP_PTS 1024
#define TP_STRIDE 17           // half2 units; odd -> conflict-free STS

struct ResArr { int r[N_LEVELS]; };

// level-major half2 scratch (carrying the 2^14 prescale): 128 MB
__device__ __half2 g_scr[(size_t)MAX_POINTS * N_LEVELS];

__global__ void __launch_bounds__(CTA_THREADS)
hash_enc4d_smem_kernel(const float* __restrict__ coords,
                       const float* __restrict__ ts,
                       const float* __restrict__ tables,
                       ResArr res, int n, int pts_per_cta)
{
    extern __shared__ __half2 s_tbl[];  // 32768 entries = 128 KB

    const int l = blockIdx.x;  // level fastest-varying: co-resident levels share coords in L2

    // Load fp32 table slice and convert inline to prescaled half2.
    // 32768 entries = 16384 float4 (2 entries each) -> 16 iters/thread.
    {
        const float4* __restrict__ src = (const float4*)(tables + (size_t)l * HASHMAP_SIZE * 2);
#pragma unroll
        for (int i = threadIdx.x; i < HASHMAP_SIZE / 2; i += CTA_THREADS) {
            float4 v = src[i];
            s_tbl[2 * i + 0] = __floats2half2_rn(v.x * 16384.0f, v.y * 16384.0f);
            s_tbl[2 * i + 1] = __floats2half2_rn(v.z * 16384.0f, v.w * 16384.0f);
        }
    }
    __syncthreads();

    const float rf = (float)res.r[l];
    const uint32_t P1 = 2654435761u, P2 = 805459861u, P3 = 3674653429u;
    __half2* __restrict__ sc = g_scr + (size_t)l * n;

    const int base = blockIdx.y * pts_per_cta;
    const int end = min(base + pts_per_cta, n);

    for (int p = base + threadIdx.x; p < end; p += CTA_THREADS) {
        float x = (coords[3 * p + 0] + 50.0f) / 100.0f;
        float y = (coords[3 * p + 1] + 50.0f) / 100.0f;
        float z = (coords[3 * p + 2] + 50.0f) / 100.0f;
        float t = ts[p];
        t = fminf(fmaxf(t, 0.0f), 1.0f);

        float sx = x * rf, sy = y * rf, sz = z * rf, st = t * rf;
        float gxf = floorf(sx), gyf = floorf(sy), gzf = floorf(sz), gtf = floorf(st);
        float fx = sx - gxf, fy = sy - gyf, fz = sz - gzf, ft = st - gtf;

        uint32_t gx = (uint32_t)(int)gxf;
        uint32_t gy = (uint32_t)(int)gyf;
        uint32_t gz = (uint32_t)(int)gzf;
        uint32_t gt = (uint32_t)(int)gtf;

        uint32_t tx0 = gx,      tx1 = gx + 1u;
        uint32_t ty0 = gy * P1, ty1 = ty0 + P1;
        uint32_t tz0 = gz * P2, tz1 = tz0 + P2;
        uint32_t tt0 = gt * P3, tt1 = tt0 + P3;

        uint32_t hxy[4], hzt[4];
        hxy[0] = tx0 ^ ty0; hxy[1] = tx1 ^ ty0;
        hxy[2] = tx0 ^ ty1; hxy[3] = tx1 ^ ty1;
        hzt[0] = tz0 ^ tt0; hzt[1] = tz1 ^ tt0;
        hzt[2] = tz0 ^ tt1; hzt[3] = tz1 ^ tt1;

        float ux = 1.0f - fx, uy = 1.0f - fy, uz = 1.0f - fz, ut = 1.0f - ft;
        float wxy[4], wzt[4];
        wxy[0] = ux * uy; wxy[1] = fx * uy; wxy[2] = ux * fy; wxy[3] = fx * fy;
        wzt[0] = uz * ut; wzt[1] = fz * ut; wzt[2] = uz * ft; wzt[3] = fz * ft;

        float a0 = 0.0f, a1 = 0.0f;
#pragma unroll
        for (int j = 0; j < 4; ++j) {
#pragma unroll
            for (int i = 0; i < 4; ++i) {
                uint32_t idx = (hxy[i] ^ hzt[j]) & HASH_MASK;
                float2 f = __half22float2(s_tbl[idx]);
                float w = wxy[i] * wzt[j];
                a0 = fmaf(w, f.x, a0);
                a1 = fmaf(w, f.y, a1);
            }
        }
        // coalesced half2 store, keeps the 2^14 prescale (values in fp16-normal range)
        sc[p] = __floats2half2_rn(a0, a1);
    }
}

// Transpose + descale: g_scr[l][p] (half2, prescaled) -> out[p][l] (float2).
// Tile 1024 pts x 16 levels, row stride 17 half2 -> conflict-free STS, ~2-way LDS.
__global__ void __launch_bounds__(TP_THREADS)
transpose_kernel(float* __restrict__ out, int n)
{
    __shared__ __half2 tile[TP_PTS * TP_STRIDE];  // 1024*17*4 = 69632 B

    const int base = blockIdx.x * TP_PTS;
    float4* __restrict__ out4 = (float4*)out;

    if (base + TP_PTS <= n) {
        // ---- fast path: full tile, no bounds checks ----
#pragma unroll
        for (int l = 0; l < N_LEVELS; ++l) {
            const __half2* __restrict__ sc = g_scr + (size_t)l * n + base;
#pragma unroll
            for (int k = 0; k < TP_PTS / TP_THREADS; ++k) {
                int i = threadIdx.x + k * TP_THREADS;
                tile[i * TP_STRIDE + l] = sc[i];
            }
        }
        __syncthreads();

#pragma unroll
        for (int k = 0; k < (TP_PTS * 8) / TP_THREADS; ++k) {
            int idx = threadIdx.x + k * TP_THREADS;
            int pt = idx >> 3;
            int q  = idx & 7;
            float2 f0 = __half22float2(tile[pt * TP_STRIDE + 2 * q]);
            float2 f1 = __half22float2(tile[pt * TP_STRIDE + 2 * q + 1]);
            out4[(size_t)(base + pt) * 8 + q] =
                make_float4(f0.x * 0x1p-14f, f0.y * 0x1p-14f,
                            f1.x * 0x1p-14f, f1.y * 0x1p-14f);
        }
    } else {
        // ---- tail path ----
#pragma unroll
        for (int l = 0; l < N_LEVELS; ++l) {
            const __half2* __restrict__ sc = g_scr + (size_t)l * n;
            for (int i = threadIdx.x; i < TP_PTS; i += TP_THREADS) {
                int p = base + i;
                tile[i * TP_STRIDE + l] = (p < n) ? sc[p]
                                                  : __half2half2(__float2half(0.0f));
            }
        }
        __syncthreads();

        for (int idx = threadIdx.x; idx < TP_PTS * 8; idx += TP_THREADS) {
            int pt = idx >> 3;
            int q  = idx & 7;
            int p  = base + pt;
            if (p < n) {
                float2 f0 = __half22float2(tile[pt * TP_STRIDE + 2 * q]);
                float2 f1 = __half22float2(tile[pt * TP_STRIDE + 2 * q + 1]);
                out4[(size_t)p * 8 + q] =
                    make_float4(f0.x * 0x1p-14f, f0.y * 0x1p-14f,
                                f1.x * 0x1p-14f, f1.y * 0x1p-14f);
            }
        }
    }
}

extern "C" void kernel_launch(void* const* d_in, const int* in_sizes, int n_in,
                              void* d_out, int out_size)
{
    const float* coords = (const float*)d_in[0];
    const float* ts     = (const float*)d_in[1];
    const float* tables = (const float*)d_in[2];
    float* out          = (float*)d_out;

    int n = in_sizes[0] / 3;

    ResArr ra;
    for (int l = 0; l < N_LEVELS; ++l) {
        double f = (double)l / 15.0;
        double v = exp(log(16.0) * (1.0 - f) + log(512.0) * f);
        ra.r[l] = (int)v;
    }

    const int smem_main = HASHMAP_SIZE * (int)sizeof(__half2);  // 131072
    const int smem_tp   = TP_PTS * TP_STRIDE * (int)sizeof(__half2);  // 69632
    static int configured = 0;
    if (!configured) {
        cudaFuncSetAttribute(hash_enc4d_smem_kernel,
                             cudaFuncAttributeMaxDynamicSharedMemorySize, smem_main);
        cudaFuncSetAttribute(transpose_kernel,
                             cudaFuncAttributeMaxDynamicSharedMemorySize, smem_tp);
        configured = 1;
    }

    // 1) single-wave level-fastest encode -> half2 level-major scratch
    //    (table converted to prescaled half2 inline during the smem load)
    int pts_per_cta = (n + N_RANGES - 1) / N_RANGES;
    dim3 grid(N_LEVELS, N_RANGES);
    hash_enc4d_smem_kernel<<<grid, CTA_THREADS, smem_main>>>(coords, ts, tables,
                                                             ra, n, pts_per_cta);

    // 2) conflict-free transpose + descale -> point-major fp32 output
    int tp_blocks = (n + TP_PTS - 1) / TP_PTS;
    transpose_kernel<<<tp_blocks, TP_THREADS, smem_tp>>>(out, n);
}

// round 7
// speedup vs baseline: 1.3594x; 1.3594x over previous
#include <cuda_runtime.h>
#include <cuda_fp16.h>
#include <math.h>
#include <stdint.h>

#define N_LEVELS 16
#define HASH_MASK 32767u
#define HASHMAP_SIZE 32768
#define PTS_PER_CTA 54272      // 37 ranges * 16 levels = 592 CTAs = 4 full waves
#define CTA_THREADS 1024
#define MAX_POINTS 2000000

#define TP_THREADS 1024
#define TP_PTS 1024
#define TP_STRIDE 17           // half2 units; odd -> conflict-free STS

struct ResArr  { int   r[N_LEVELS]; };
struct ScaleArr{ float s[N_LEVELS]; };   // res/100, host-computed

// level-major half2 scratch (carrying the 2^14 prescale): 128 MB
__device__ __half2 g_scr[(size_t)MAX_POINTS * N_LEVELS];

__global__ void __launch_bounds__(CTA_THREADS)
hash_enc4d_smem_kernel(const float* __restrict__ coords,
                       const float* __restrict__ ts,
                       const float* __restrict__ tables,
                       ResArr res, ScaleArr scl, int n)
{
    extern __shared__ __half2 s_tbl[];  // 32768 entries = 128 KB

    const int l = blockIdx.x;  // level fastest-varying: co-resident levels share coords in L2

    // Load fp32 table slice, convert inline to prescaled half2.
    {
        const float4* __restrict__ src = (const float4*)(tables + (size_t)l * HASHMAP_SIZE * 2);
#pragma unroll
        for (int i = threadIdx.x; i < HASHMAP_SIZE / 2; i += CTA_THREADS) {
            float4 v = src[i];
            s_tbl[2 * i + 0] = __floats2half2_rn(v.x * 16384.0f, v.y * 16384.0f);
            s_tbl[2 * i + 1] = __floats2half2_rn(v.z * 16384.0f, v.w * 16384.0f);
        }
    }
    __syncthreads();

    const float rf = (float)res.r[l];
    const float sl = scl.s[l];          // res/100 (xyz scale, fused normalize+resolution)
    const uint32_t P1 = 2654435761u, P2 = 805459861u, P3 = 3674653429u;
    __half2* __restrict__ sc = g_scr + (size_t)l * n;

    const int base = blockIdx.y * PTS_PER_CTA;
    const int end = min(base + PTS_PER_CTA, n);

    for (int p = base + threadIdx.x; p < end; p += CTA_THREADS) {
        float sx = (coords[3 * p + 0] + 50.0f) * sl;
        float sy = (coords[3 * p + 1] + 50.0f) * sl;
        float sz = (coords[3 * p + 2] + 50.0f) * sl;
        float t  = ts[p];
        t = fminf(fmaxf(t, 0.0f), 1.0f);
        float st = t * rf;

        float gxf = floorf(sx), gyf = floorf(sy), gzf = floorf(sz), gtf = floorf(st);
        float fx = sx - gxf, fy = sy - gyf, fz = sz - gzf, ft = st - gtf;

        uint32_t gx = (uint32_t)(int)gxf;
        uint32_t gy = (uint32_t)(int)gyf;
        uint32_t gz = (uint32_t)(int)gzf;
        uint32_t gt = (uint32_t)(int)gtf;

        uint32_t tx0 = gx,      tx1 = gx + 1u;
        uint32_t ty0 = gy * P1, ty1 = ty0 + P1;
        uint32_t tz0 = gz * P2, tz1 = tz0 + P2;
        uint32_t tt0 = gt * P3, tt1 = tt0 + P3;

        uint32_t hxy[4], hzt[4];
        hxy[0] = tx0 ^ ty0; hxy[1] = tx1 ^ ty0;
        hxy[2] = tx0 ^ ty1; hxy[3] = tx1 ^ ty1;
        hzt[0] = tz0 ^ tt0; hzt[1] = tz1 ^ tt0;
        hzt[2] = tz0 ^ tt1; hzt[3] = tz1 ^ tt1;

        float ux = 1.0f - fx, uy = 1.0f - fy, uz = 1.0f - fz, ut = 1.0f - ft;
        float wxy[4], wzt[4];
        wxy[0] = ux * uy; wxy[1] = fx * uy; wxy[2] = ux * fy; wxy[3] = fx * fy;
        wzt[0] = uz * ut; wzt[1] = fz * ut; wzt[2] = uz * ft; wzt[3] = fz * ft;

        float a0 = 0.0f, a1 = 0.0f;
#pragma unroll
        for (int j = 0; j < 4; ++j) {
#pragma unroll
            for (int i = 0; i < 4; ++i) {
                uint32_t idx = (hxy[i] ^ hzt[j]) & HASH_MASK;
                float2 f = __half22float2(s_tbl[idx]);
                float w = wxy[i] * wzt[j];
                a0 = fmaf(w, f.x, a0);
                a1 = fmaf(w, f.y, a1);
            }
        }
        // coalesced half2 store, keeps the 2^14 prescale
        sc[p] = __floats2half2_rn(a0, a1);
    }
}

// Transpose + descale: g_scr[l][p] (half2, prescaled) -> out[p][l*2..] (fp32).
// 1024 pts x 16 levels tile, stride 17 -> conflict-free STS, ~2-way LDS.
// 1024 threads, 69.6 KB smem -> 2 CTAs/SM -> full warp occupancy.
__global__ void __launch_bounds__(TP_THREADS)
transpose_kernel(float* __restrict__ out, int n)
{
    extern __shared__ __half2 tile[];  // 1024*17*4 = 69632 B

    const int base = blockIdx.x * TP_PTS;
    float4* __restrict__ out4 = (float4*)out;

    if (base + TP_PTS <= n) {
        // fast path: full tile
#pragma unroll
        for (int l = 0; l < N_LEVELS; ++l) {
            const __half2* __restrict__ sc = g_scr + (size_t)l * n + base;
            tile[threadIdx.x * TP_STRIDE + l] = sc[threadIdx.x];
        }
        __syncthreads();

#pragma unroll
        for (int k = 0; k < 8; ++k) {
            int idx = threadIdx.x + k * TP_THREADS;
            int pt = idx >> 3;
            int q  = idx & 7;
            float2 f0 = __half22float2(tile[pt * TP_STRIDE + 2 * q]);
            float2 f1 = __half22float2(tile[pt * TP_STRIDE + 2 * q + 1]);
            out4[(size_t)(base + pt) * 8 + q] =
                make_float4(f0.x * 0x1p-14f, f0.y * 0x1p-14f,
                            f1.x * 0x1p-14f, f1.y * 0x1p-14f);
        }
    } else {
        // tail path
#pragma unroll
        for (int l = 0; l < N_LEVELS; ++l) {
            const __half2* __restrict__ sc = g_scr + (size_t)l * n;
            int p = base + threadIdx.x;
            tile[threadIdx.x * TP_STRIDE + l] =
                (p < n) ? sc[p] : __half2half2(__float2half(0.0f));
        }
        __syncthreads();

        for (int k = 0; k < 8; ++k) {
            int idx = threadIdx.x + k * TP_THREADS;
            int pt = idx >> 3;
            int q  = idx & 7;
            int p  = base + pt;
            if (p < n) {
                float2 f0 = __half22float2(tile[pt * TP_STRIDE + 2 * q]);
                float2 f1 = __half22float2(tile[pt * TP_STRIDE + 2 * q + 1]);
                out4[(size_t)p * 8 + q] =
                    make_float4(f0.x * 0x1p-14f, f0.y * 0x1p-14f,
                                f1.x * 0x1p-14f, f1.y * 0x1p-14f);
            }
        }
    }
}

extern "C" void kernel_launch(void* const* d_in, const int* in_sizes, int n_in,
                              void* d_out, int out_size)
{
    const float* coords = (const float*)d_in[0];
    const float* ts     = (const float*)d_in[1];
    const float* tables = (const float*)d_in[2];
    float* out          = (float*)d_out;

    int n = in_sizes[0] / 3;

    ResArr ra; ScaleArr sa;
    for (int l = 0; l < N_LEVELS; ++l) {
        double f = (double)l / 15.0;
        double v = exp(log(16.0) * (1.0 - f) + log(512.0) * f);
        ra.r[l] = (int)v;
        sa.s[l] = (float)((double)ra.r[l] / 100.0);
    }

    const int smem_main = HASHMAP_SIZE * (int)sizeof(__half2);        // 131072
    const int smem_tp   = TP_PTS * TP_STRIDE * (int)sizeof(__half2);  // 69632
    static int configured = 0;
    if (!configured) {
        cudaFuncSetAttribute(hash_enc4d_smem_kernel,
                             cudaFuncAttributeMaxDynamicSharedMemorySize, smem_main);
        cudaFuncSetAttribute(transpose_kernel,
                             cudaFuncAttributeMaxDynamicSharedMemorySize, smem_tp);
        configured = 1;
    }

    // 1) 4-wave level-fastest encode -> half2 level-major scratch
    dim3 grid(N_LEVELS, (n + PTS_PER_CTA - 1) / PTS_PER_CTA);
    hash_enc4d_smem_kernel<<<grid, CTA_THREADS, smem_main>>>(coords, ts, tables,
                                                             ra, sa, n);

    // 2) full-occupancy conflict-free transpose + descale
    int tp_blocks = (n + TP_PTS - 1) / TP_PTS;
    transpose_kernel<<<tp_blocks, TP_THREADS, smem_tp>>>(out, n);
}